// round 7
// baseline (speedup 1.0000x reference)
#include <cuda_runtime.h>
#include <cstdint>

#define TT 32     // simulation length
#define LL 4      // number of cores
#define BB 128    // batch
#define HH 1024   // neurons/axons per core

__device__ unsigned g_bitsA[BB * HH];
__device__ unsigned g_bitsB[BB * HH];

// Packed f32x2 add: two independent IEEE fp32 rn adds in ONE instruction
// (Blackwell sm_100+). Each lane == fl(a+b), bit-identical to scalar FADD.
#define ADD_F32X2(acc, inc) \
    asm("add.rn.f32x2 %0, %1, %2;" : "=l"(acc) : "l"(acc), "l"(inc))
#define PACK_F32X2(out, lo, hi) \
    asm("mov.b64 %0, {%1, %2};" : "=l"(out) : "f"(lo), "f"(hi))
#define UNPACK_F32X2(lo, hi, in) \
    asm("mov.b64 {%0, %1}, %2;" : "=f"(lo), "=f"(hi) : "l"(in))

// ---------------------------------------------------------------------------
// Spike encoding: bit-exact fp32 mirror of to_uniform_spikes.
// ---------------------------------------------------------------------------
__global__ void encode_kernel(const float* __restrict__ x, unsigned* __restrict__ U)
{
    int idx = blockIdx.x * blockDim.x + threadIdx.x;
    if (idx >= BB * HH) return;
    float xv = x[idx];
    float Nf = rintf(__fmul_rn(xv, 32.0f));
    int   N  = (int)Nf;
    unsigned bits = 0u;
    if (N >= TT) {
        bits = 0xFFFFFFFFu;
    } else if (N > 0) {
        float spacing = __fdiv_rn(32.0f, (float)N);
        float fN = (float)N;
        #pragma unroll
        for (int t = 0; t < TT; ++t) {
            float c = (float)t;
            float q = floorf(__fdiv_rn(c, spacing));
            float r = fmodf(c, spacing);         // exact remainder (matches lax.rem)
            if (q < fN && floorf(r) == 0.0f) bits |= (1u << t);
        }
    }
    U[idx] = bits;
}

// ---------------------------------------------------------------------------
// One layer. CORRECTNESS-CRITICAL invariant: for every (b, n, t), z[t] is
// accumulated as a SINGLE fp32 accumulator over axons a in STRICT ASCENDING
// order. Do not reassociate, split accumulators, or reorder the a loop.
// The f32x2 packing is register layout only: each component is its own
// correctly-rounded sequential chain.
//
// Structure = Round-4 known-good (2 neurons/lane, 2048 warps): each thread
// owns n0 = nbase+lane and n1 = nbase+32+lane, sharing one warp-uniform
// spike mask u. Weights as float2 in smem (one LDS.64), accumulators as
// packed f32x2 -> ONE add.rn.f32x2 per active (a,t).
//
// Block = 128 threads = 4 b-rows x 32 lanes; warp <-> one b row, so u is
// warp-uniform and branches never diverge.
// ---------------------------------------------------------------------------
template<int LAST>
__global__ void __launch_bounds__(128) layer_kernel(
    const unsigned* __restrict__ Uin,
    const float*    __restrict__ W,        // (HH neurons, HH axons) row-major
    const float*    __restrict__ thresholds,
    int layer,
    unsigned* __restrict__ Uout,
    float*    __restrict__ out)
{
    __shared__ float2   sW[32][33];   // [a_local][lane]: (.x = n0 w, .y = n1 w), padded
    __shared__ unsigned sU[4][32];    // [b_local][a_local]

    const int tx    = threadIdx.x;
    const int lane  = tx & 31;
    const int row   = tx >> 5;        // b within tile == warp id
    const int nbase = blockIdx.x * 64;
    const int bbase = blockIdx.y * 4;
    const int n0    = nbase + lane;
    const int n1    = nbase + 32 + lane;
    const int b     = bbase + row;
    const float thr = thresholds[layer];

    unsigned long long zp[TT];        // packed (z0[t], z1[t])
    #pragma unroll
    for (int t = 0; t < TT; ++t) zp[t] = 0ULL;   // (0.0f, 0.0f)

    for (int a0 = 0; a0 < HH; a0 += 32) {
        // Stage W tile: 64 n x 32 a (same as R4-passing layout/pattern).
        #pragma unroll
        for (int i = 0; i < 16; ++i) {
            int lin = tx + i * 128;
            int wn  = lin >> 5;               // 0..63
            int wa  = lin & 31;
            float v = W[(size_t)(nbase + wn) * HH + (a0 + wa)];
            if (wn < 32) sW[wa][wn].x = v;
            else         sW[wa][wn - 32].y = v;
        }
        // Stage spike masks: 4 b x 32 a (one word per thread)
        sU[row][lane] = Uin[(bbase + row) * HH + (a0 + lane)];
        __syncthreads();

        #pragma unroll 4
        for (int a = 0; a < 32; ++a) {          // ascending a: required for exactness
            unsigned u = sU[row][a];            // warp-uniform (LDS broadcast)
            if (u == 0u) continue;              // exact no-op
            float2 w = sW[a][lane];             // LDS.64, conflict-free
            unsigned long long wp;              // bit-cast: same register pair
            PACK_F32X2(wp, w.x, w.y);
            #pragma unroll
            for (int t = 0; t < TT; ++t) {
                if (u & (1u << t)) {
                    ADD_F32X2(zp[t], wp);       // 2 chains, ONE instruction
                }
            }
        }
        __syncthreads();
    }

    // LIF recurrence over 32 cycles, all in registers (scalar, as reference).
    float m0 = 0.0f, m1 = 0.0f;
    unsigned bits0 = 0u, bits1 = 0u;
    #pragma unroll
    for (int t = 0; t < TT; ++t) {
        float a0v, a1v;
        UNPACK_F32X2(a0v, a1v, zp[t]);
        m0 = __fadd_rn(m0, a0v);
        if (thr < m0) { m0 = __fsub_rn(m0, thr); bits0 |= (1u << t); }
        m1 = __fadd_rn(m1, a1v);
        if (thr < m1) { m1 = __fsub_rn(m1, thr); bits1 |= (1u << t); }
    }

    if (LAST) {
        out[b * HH + n0] = (float)__popc(bits0) * (1.0f / 32.0f);
        out[b * HH + n1] = (float)__popc(bits1) * (1.0f / 32.0f);
    } else {
        Uout[b * HH + n0] = bits0;
        Uout[b * HH + n1] = bits1;
    }
}

// ---------------------------------------------------------------------------
// Launch: encode -> 4 layer passes (ping-pong bitmask buffers).
// ---------------------------------------------------------------------------
extern "C" void kernel_launch(void* const* d_in, const int* in_sizes, int n_in,
                              void* d_out, int out_size)
{
    const float* x   = (const float*)d_in[0];                 // (128,1024)
    const float* Wts = (const float*)d_in[1];                 // (4,1024,1024)
    const float* thr = (const float*)d_in[2];                 // (4,)
    float* out = (float*)d_out;                               // (128,1024)

    static unsigned* pA = nullptr;
    static unsigned* pB = nullptr;
    if (!pA) {
        cudaGetSymbolAddress((void**)&pA, g_bitsA);
        cudaGetSymbolAddress((void**)&pB, g_bitsB);
    }

    encode_kernel<<<(BB * HH + 255) / 256, 256>>>(x, pA);

    dim3 grid(HH / 64, BB / 4);   // (16, 32) = 512 blocks of 128 threads
    const size_t Wstride = (size_t)HH * HH;

    layer_kernel<0><<<grid, 128>>>(pA, Wts + 0 * Wstride, thr, 0, pB, nullptr);
    layer_kernel<0><<<grid, 128>>>(pB, Wts + 1 * Wstride, thr, 1, pA, nullptr);
    layer_kernel<0><<<grid, 128>>>(pA, Wts + 2 * Wstride, thr, 2, pB, nullptr);
    layer_kernel<1><<<grid, 128>>>(pB, Wts + 3 * Wstride, thr, 3, nullptr, out);
}

// round 9
// speedup vs baseline: 1.1420x; 1.1420x over previous
#include <cuda_runtime.h>
#include <cstdint>

#define TT 32     // simulation length
#define LL 4      // number of cores
#define BB 128    // batch
#define HH 1024   // neurons/axons per core

__device__ unsigned g_bitsA[BB * HH];
__device__ unsigned g_bitsB[BB * HH];

// ---------------------------------------------------------------------------
// Spike encoding: bit-exact fp32 mirror of to_uniform_spikes.
// ---------------------------------------------------------------------------
__global__ void encode_kernel(const float* __restrict__ x, unsigned* __restrict__ U)
{
    int idx = blockIdx.x * blockDim.x + threadIdx.x;
    if (idx >= BB * HH) return;
    float xv = x[idx];
    float Nf = rintf(__fmul_rn(xv, 32.0f));
    int   N  = (int)Nf;
    unsigned bits = 0u;
    if (N >= TT) {
        bits = 0xFFFFFFFFu;
    } else if (N > 0) {
        float spacing = __fdiv_rn(32.0f, (float)N);
        float fN = (float)N;
        #pragma unroll
        for (int t = 0; t < TT; ++t) {
            float c = (float)t;
            float q = floorf(__fdiv_rn(c, spacing));
            float r = fmodf(c, spacing);         // exact remainder (matches lax.rem)
            if (q < fN && floorf(r) == 0.0f) bits |= (1u << t);
        }
    }
    U[idx] = bits;
}

// ---------------------------------------------------------------------------
// One layer, t-split. CORRECTNESS-CRITICAL invariant: for every (b, n, t),
// z[t] is accumulated as a SINGLE fp32 accumulator over axons a in STRICT
// ASCENDING order. Each cycle t is owned entirely by ONE warp, so the
// t-split does not alter any chain.
//
// Block = 128 threads = 4 warps: warp w -> (b_row = w>>1, t_half = w&1).
// Both t-half warps of a b-row share sU and sW. Each warp scans only its
// 16 bits (uh), keeping total bit-scan work constant while DOUBLING the
// resident warp count (4096 total) to push issue% up the measured
// occupancy->issue curve (1024w:45%, 2048w:65%, 4096w:77%).
//
// Each thread owns 2 neurons (n0 = nbase+lane, n1 = nbase+32+lane); plain
// C `if(bit) z+=w` so ptxas predicates (NO inline-asm adds -- R7 lesson).
//
// Epilogue: t-hi warp stores its z[16..31] to padded smem (stride 17,
// conflict-free); t-lo warp runs the full 32-step membrane scan.
// ---------------------------------------------------------------------------
template<int LAST>
__global__ void __launch_bounds__(128, 6) layer_kernel(
    const unsigned* __restrict__ Uin,
    const float*    __restrict__ W,        // (HH neurons, HH axons) row-major
    const float*    __restrict__ thresholds,
    int layer,
    unsigned* __restrict__ Uout,
    float*    __restrict__ out)
{
    __shared__ float2   sW[32][33];       // [a_local][lane]: (.x=n0 w, .y=n1 w), pad
    __shared__ unsigned sU[2][32];        // [b_local][a_local]
    __shared__ float    zx[2][2][32][17]; // [b_local][chain][lane][t-16], pad 17

    const int tx    = threadIdx.x;
    const int lane  = tx & 31;
    const int wid   = tx >> 5;        // 0..3
    const int row   = wid >> 1;       // b within tile (2 rows)
    const int thalf = wid & 1;        // 0: t=0..15, 1: t=16..31
    const int nbase = blockIdx.x * 64;
    const int bbase = blockIdx.y * 2;
    const int n0    = nbase + lane;
    const int n1    = nbase + 32 + lane;
    const int b     = bbase + row;
    const float thr = thresholds[layer];

    float z0[16], z1[16];             // this warp's 16 cycles only
    #pragma unroll
    for (int t = 0; t < 16; ++t) { z0[t] = 0.0f; z1[t] = 0.0f; }

    const int tshift = thalf * 16;

    for (int a0 = 0; a0 < HH; a0 += 32) {
        // Stage W tile: 64 n x 32 a (proven R4 pattern, scalar STS).
        #pragma unroll
        for (int i = 0; i < 16; ++i) {
            int lin = tx + i * 128;
            int wn  = lin >> 5;               // 0..63
            int wa  = lin & 31;
            float v = W[(size_t)(nbase + wn) * HH + (a0 + wa)];
            if (wn < 32) sW[wa][wn].x = v;
            else         sW[wa][wn - 32].y = v;
        }
        // Stage spike masks: 2 b x 32 a
        if (tx < 64) sU[tx >> 5][tx & 31] = Uin[(bbase + (tx >> 5)) * HH + (a0 + (tx & 31))];
        __syncthreads();

        #pragma unroll 4
        for (int a = 0; a < 32; ++a) {            // ascending a: required for exactness
            unsigned uh = (sU[row][a] >> tshift) & 0xFFFFu;  // this warp's 16 bits
            if (uh == 0u) continue;               // exact no-op; skips more often than full u
            float2 w = sW[a][lane];               // LDS.64, conflict-free
            #pragma unroll
            for (int t = 0; t < 16; ++t) {
                if (uh & (1u << t)) {             // predicated adds (plain C)
                    z0[t] += w.x;
                    z1[t] += w.y;
                }
            }
        }
        __syncthreads();
    }

    // t-hi warps publish their z to smem (pad 17 -> conflict-free).
    if (thalf == 1) {
        #pragma unroll
        for (int t = 0; t < 16; ++t) {
            zx[row][0][lane][t] = z0[t];
            zx[row][1][lane][t] = z1[t];
        }
    }
    __syncthreads();

    // t-lo warps run the full 32-step LIF recurrence (bit-exact scalar scan).
    if (thalf == 0) {
        float m0 = 0.0f, m1 = 0.0f;
        unsigned bits0 = 0u, bits1 = 0u;
        #pragma unroll
        for (int t = 0; t < 16; ++t) {
            m0 = __fadd_rn(m0, z0[t]);
            if (thr < m0) { m0 = __fsub_rn(m0, thr); bits0 |= (1u << t); }
            m1 = __fadd_rn(m1, z1[t]);
            if (thr < m1) { m1 = __fsub_rn(m1, thr); bits1 |= (1u << t); }
        }
        #pragma unroll
        for (int t = 0; t < 16; ++t) {
            float h0 = zx[row][0][lane][t];
            float h1 = zx[row][1][lane][t];
            m0 = __fadd_rn(m0, h0);
            if (thr < m0) { m0 = __fsub_rn(m0, thr); bits0 |= (1u << (t + 16)); }
            m1 = __fadd_rn(m1, h1);
            if (thr < m1) { m1 = __fsub_rn(m1, thr); bits1 |= (1u << (t + 16)); }
        }

        if (LAST) {
            out[b * HH + n0] = (float)__popc(bits0) * (1.0f / 32.0f);
            out[b * HH + n1] = (float)__popc(bits1) * (1.0f / 32.0f);
        } else {
            Uout[b * HH + n0] = bits0;
            Uout[b * HH + n1] = bits1;
        }
    }
}

// ---------------------------------------------------------------------------
// Launch: encode -> 4 layer passes (ping-pong bitmask buffers).
// ---------------------------------------------------------------------------
extern "C" void kernel_launch(void* const* d_in, const int* in_sizes, int n_in,
                              void* d_out, int out_size)
{
    const float* x   = (const float*)d_in[0];                 // (128,1024)
    const float* Wts = (const float*)d_in[1];                 // (4,1024,1024)
    const float* thr = (const float*)d_in[2];                 // (4,)
    float* out = (float*)d_out;                               // (128,1024)

    static unsigned* pA = nullptr;
    static unsigned* pB = nullptr;
    if (!pA) {
        cudaGetSymbolAddress((void**)&pA, g_bitsA);
        cudaGetSymbolAddress((void**)&pB, g_bitsB);
    }

    encode_kernel<<<(BB * HH + 255) / 256, 256>>>(x, pA);

    dim3 grid(HH / 64, BB / 2);   // (16, 64) = 1024 blocks of 128 threads (4096 warps)
    const size_t Wstride = (size_t)HH * HH;

    layer_kernel<0><<<grid, 128>>>(pA, Wts + 0 * Wstride, thr, 0, pB, nullptr);
    layer_kernel<0><<<grid, 128>>>(pB, Wts + 1 * Wstride, thr, 1, pA, nullptr);
    layer_kernel<0><<<grid, 128>>>(pA, Wts + 2 * Wstride, thr, 2, pB, nullptr);
    layer_kernel<1><<<grid, 128>>>(pB, Wts + 3 * Wstride, thr, 3, nullptr, out);
}

// round 10
// speedup vs baseline: 1.6315x; 1.4287x over previous
#include <cuda_runtime.h>
#include <cstdint>

#define TT 32     // simulation length
#define LL 4      // number of cores
#define BB 128    // batch
#define HH 1024   // neurons/axons per core

__device__ unsigned g_bitsA[BB * HH];
__device__ unsigned g_bitsB[BB * HH];

// ---------------------------------------------------------------------------
// Spike encoding: bit-exact fp32 mirror of to_uniform_spikes.
// ---------------------------------------------------------------------------
__global__ void encode_kernel(const float* __restrict__ x, unsigned* __restrict__ U)
{
    int idx = blockIdx.x * blockDim.x + threadIdx.x;
    if (idx >= BB * HH) return;
    float xv = x[idx];
    float Nf = rintf(__fmul_rn(xv, 32.0f));
    int   N  = (int)Nf;
    unsigned bits = 0u;
    if (N >= TT) {
        bits = 0xFFFFFFFFu;
    } else if (N > 0) {
        float spacing = __fdiv_rn(32.0f, (float)N);
        float fN = (float)N;
        #pragma unroll
        for (int t = 0; t < TT; ++t) {
            float c = (float)t;
            float q = floorf(__fdiv_rn(c, spacing));
            float r = fmodf(c, spacing);         // exact remainder (matches lax.rem)
            if (q < fN && floorf(r) == 0.0f) bits |= (1u << t);
        }
    }
    U[idx] = bits;
}

// ---------------------------------------------------------------------------
// One layer. CORRECTNESS-CRITICAL invariant: for every (b, n, t), z[t] is
// accumulated as a SINGLE fp32 accumulator over axons a in STRICT ASCENDING
// order. Do not reassociate, split accumulators, or reorder the a loop.
//
// Champion structure (R4: 2 chains/lane, 2048 warps) with three refinements:
//   1. 8 b-rows per block (256 thr): W-tile staging amortized over 8 warps,
//      half the blocks -> half the staging instructions.
//   2. Double-buffered sW/sU: ONE __syncthreads per tile (was two), and the
//      next tile's LDGs issue before this tile's compute (latency overlap).
//   3. w loaded before the u==0 test so the LDS does not serialize behind
//      the branch.
//
// Plain C `if(bit) z+=w` (ptxas predicate/skip-tree -- R7 lesson: no asm).
// Warp <-> one b row, so u is warp-uniform; branches never diverge.
// ---------------------------------------------------------------------------
template<int LAST>
__global__ void __launch_bounds__(256, 2) layer_kernel(
    const unsigned* __restrict__ Uin,
    const float*    __restrict__ W,        // (HH neurons, HH axons) row-major
    const float*    __restrict__ thresholds,
    int layer,
    unsigned* __restrict__ Uout,
    float*    __restrict__ out)
{
    __shared__ float2   sW[2][32][33];   // [buf][a_local][lane]: (.x=n0 w,.y=n1 w), pad
    __shared__ unsigned sU[2][8][32];    // [buf][b_local][a_local]

    const int tx    = threadIdx.x;
    const int lane  = tx & 31;
    const int row   = tx >> 5;        // 0..7: b within tile == warp id
    const int nbase = blockIdx.x * 64;
    const int bbase = blockIdx.y * 8;
    const int n0    = nbase + lane;
    const int n1    = nbase + 32 + lane;
    const int b     = bbase + row;
    const float thr = thresholds[layer];

    float z0[TT], z1[TT];
    #pragma unroll
    for (int t = 0; t < TT; ++t) { z0[t] = 0.0f; z1[t] = 0.0f; }

    // Tile stager: 64 n x 32 a weights (8 floats/thread) + 8x32 spike words.
    auto stage = [&](int buf, int a0) {
        #pragma unroll
        for (int i = 0; i < 8; ++i) {
            int lin = tx + i * 256;
            int wn  = lin >> 5;               // 0..63
            int wa  = lin & 31;               // coalesced along a
            float v = W[(size_t)(nbase + wn) * HH + (a0 + wa)];
            if (wn < 32) sW[buf][wa][wn].x = v;
            else         sW[buf][wa][wn - 32].y = v;
        }
        sU[buf][row][lane] = Uin[(bbase + row) * HH + (a0 + lane)];
    };

    stage(0, 0);
    __syncthreads();

    for (int tile = 0; tile < 32; ++tile) {
        const int buf = tile & 1;
        if (tile + 1 < 32) stage(buf ^ 1, (tile + 1) * 32);   // prefetch next tile

        #pragma unroll 4
        for (int a = 0; a < 32; ++a) {          // ascending a: required for exactness
            unsigned u = sU[buf][row][a];       // warp-uniform (LDS broadcast)
            float2 w = sW[buf][a][lane];        // LDS.64 before the test (decoupled)
            if (u == 0u) continue;              // exact no-op
            #pragma unroll
            for (int t = 0; t < TT; ++t) {
                if (u & (1u << t)) {            // predicated/skip-tree adds
                    z0[t] += w.x;
                    z1[t] += w.y;
                }
            }
        }
        __syncthreads();                        // one barrier per tile
    }

    // LIF recurrence over 32 cycles, all in registers (bit-exact scalar scan).
    float m0 = 0.0f, m1 = 0.0f;
    unsigned bits0 = 0u, bits1 = 0u;
    #pragma unroll
    for (int t = 0; t < TT; ++t) {
        m0 = __fadd_rn(m0, z0[t]);
        if (thr < m0) { m0 = __fsub_rn(m0, thr); bits0 |= (1u << t); }
        m1 = __fadd_rn(m1, z1[t]);
        if (thr < m1) { m1 = __fsub_rn(m1, thr); bits1 |= (1u << t); }
    }

    if (LAST) {
        out[b * HH + n0] = (float)__popc(bits0) * (1.0f / 32.0f);
        out[b * HH + n1] = (float)__popc(bits1) * (1.0f / 32.0f);
    } else {
        Uout[b * HH + n0] = bits0;
        Uout[b * HH + n1] = bits1;
    }
}

// ---------------------------------------------------------------------------
// Launch: encode -> 4 layer passes (ping-pong bitmask buffers).
// ---------------------------------------------------------------------------
extern "C" void kernel_launch(void* const* d_in, const int* in_sizes, int n_in,
                              void* d_out, int out_size)
{
    const float* x   = (const float*)d_in[0];                 // (128,1024)
    const float* Wts = (const float*)d_in[1];                 // (4,1024,1024)
    const float* thr = (const float*)d_in[2];                 // (4,)
    float* out = (float*)d_out;                               // (128,1024)

    static unsigned* pA = nullptr;
    static unsigned* pB = nullptr;
    if (!pA) {
        cudaGetSymbolAddress((void**)&pA, g_bitsA);
        cudaGetSymbolAddress((void**)&pB, g_bitsB);
    }

    encode_kernel<<<(BB * HH + 255) / 256, 256>>>(x, pA);

    dim3 grid(HH / 64, BB / 8);   // (16, 16) = 256 blocks of 256 threads (2048 warps)
    const size_t Wstride = (size_t)HH * HH;

    layer_kernel<0><<<grid, 256>>>(pA, Wts + 0 * Wstride, thr, 0, pB, nullptr);
    layer_kernel<0><<<grid, 256>>>(pB, Wts + 1 * Wstride, thr, 1, pA, nullptr);
    layer_kernel<0><<<grid, 256>>>(pA, Wts + 2 * Wstride, thr, 2, pB, nullptr);
    layer_kernel<1><<<grid, 256>>>(pB, Wts + 3 * Wstride, thr, 3, nullptr, out);
}

// round 13
// speedup vs baseline: 1.6376x; 1.0037x over previous
#include <cuda_runtime.h>
#include <cstdint>

#define TT 32     // simulation length
#define LL 4      // number of cores
#define BB 128    // batch
#define HH 1024   // neurons/axons per core

// Spike bitmask ping-pong buffers + pair-interleaved transposed weights.
__device__ unsigned g_bitsA[BB * HH];
__device__ unsigned g_bitsB[BB * HH];
__device__ float    g_Wtp[LL * HH * HH];   // Wtp[l][a][j], j = c*64 + s*2 + k <-> n = c*64 + k*32 + s

// ---------------------------------------------------------------------------
// Spike encoding: bit-exact fp32 mirror of to_uniform_spikes.
// ---------------------------------------------------------------------------
__global__ void encode_kernel(const float* __restrict__ x, unsigned* __restrict__ U)
{
    int idx = blockIdx.x * blockDim.x + threadIdx.x;
    if (idx >= BB * HH) return;
    float xv = x[idx];
    float Nf = rintf(__fmul_rn(xv, 32.0f));
    int   N  = (int)Nf;
    unsigned bits = 0u;
    if (N >= TT) {
        bits = 0xFFFFFFFFu;
    } else if (N > 0) {
        float spacing = __fdiv_rn(32.0f, (float)N);
        float fN = (float)N;
        #pragma unroll
        for (int t = 0; t < TT; ++t) {
            float c = (float)t;
            float q = floorf(__fdiv_rn(c, spacing));
            float r = fmodf(c, spacing);         // exact remainder (matches lax.rem)
            if (q < fN && floorf(r) == 0.0f) bits |= (1u << t);
        }
    }
    U[idx] = bits;
}

// ---------------------------------------------------------------------------
// Weight transpose + pair-interleave (runs once per launch, ~12us):
//   Wtp[l][a][c*64 + s*2 + k] = W[l][c*64 + k*32 + s][a]
// so the layer kernel's (w_n0, w_n1) for axon a is ONE coalesced LDG.64.
// Tiled through smem: coalesced reads along a, coalesced writes along j.
// ---------------------------------------------------------------------------
__global__ void transpose_kernel(const float* __restrict__ W, float* __restrict__ Wtp)
{
    __shared__ float s[64][33];
    const int c  = blockIdx.x;          // 0..15  (n column group of 64)
    const int a0 = blockIdx.y * 32;     // 0..992 (a tile)
    const int l  = blockIdx.z;          // layer
    const float* Wl = W   + (size_t)l * HH * HH;
    float*       Wt = Wtp + (size_t)l * HH * HH;
    const int tx = threadIdx.x;

    #pragma unroll
    for (int i = 0; i < 8; ++i) {       // read 64 n x 32 a, coalesced along a
        int lin = tx + i * 256;
        int wn  = lin >> 5;
        int wa  = lin & 31;
        s[wn][wa] = Wl[(size_t)(c * 64 + wn) * HH + (a0 + wa)];
    }
    __syncthreads();
    #pragma unroll
    for (int i = 0; i < 8; ++i) {       // write 32 a x 64 j, coalesced along j
        int lin = tx + i * 256;
        int ar  = lin >> 6;
        int j   = lin & 63;
        int nl  = ((j & 1) << 5) | (j >> 1);   // j = s*2+k -> n_local = k*32+s
        Wt[(size_t)(a0 + ar) * HH + c * 64 + j] = s[nl][ar];
    }
}

// ---------------------------------------------------------------------------
// One layer, smem-free. CORRECTNESS-CRITICAL invariant: for every (b, n, t),
// z[t] is a SINGLE fp32 accumulator over axons a in STRICT ASCENDING order.
// Do not reassociate, split accumulators, or reorder the a loop.
//
// One warp owns one (b, ncol) unit: 64 neurons (2 chains/lane, n1 = n0+32).
// - u masks: LDG.128 (4 axons per load), warp-uniform per lane usage.
// - weights: ONE coalesced LDG.64 per axon from the pair-interleaved Wtp.
// - software pipeline: next group's u4 + 4 w-pairs prefetched before
//   processing the current group (hides L2 latency, no barriers anywhere).
// Blocks = 64 threads (2 independent warps) -> 1024 blocks -> near-perfect
// SM balance (14 vs 13.84 warps on the busiest SM).
// Plain C `if(bit) z+=w` so ptxas emits its predicate/skip-tree (R7 lesson).
// ---------------------------------------------------------------------------
template<int LAST>
__global__ void __launch_bounds__(64) layer_kernel(
    const unsigned* __restrict__ Uin,
    const float*    __restrict__ Wp,       // this layer's Wtp
    const float*    __restrict__ thresholds,
    int layer,
    unsigned* __restrict__ Uout,
    float*    __restrict__ out)
{
    const int lane = threadIdx.x & 31;
    const int unit = blockIdx.x * 2 + (threadIdx.x >> 5);   // 0..2047
    const int b    = unit & 127;
    const int ncol = unit >> 7;                              // 0..15
    const float thr = thresholds[layer];

    float z0[TT], z1[TT];
    #pragma unroll
    for (int t = 0; t < TT; ++t) { z0[t] = 0.0f; z1[t] = 0.0f; }

    const uint4* __restrict__ Urow = reinterpret_cast<const uint4*>(Uin + b * HH);
    const float* __restrict__ Wl   = Wp + ncol * 64 + lane * 2;   // + a*HH per axon

    // Prefetch group 0.
    uint4  u4 = Urow[0];
    float2 w0 = *reinterpret_cast<const float2*>(Wl + 0 * HH);
    float2 w1 = *reinterpret_cast<const float2*>(Wl + 1 * HH);
    float2 w2 = *reinterpret_cast<const float2*>(Wl + 2 * HH);
    float2 w3 = *reinterpret_cast<const float2*>(Wl + 3 * HH);

    #define PROC(uu, ww)                                    \
        if ((uu) != 0u) {                                   \
            _Pragma("unroll")                               \
            for (int t = 0; t < TT; ++t) {                  \
                if ((uu) & (1u << t)) {                     \
                    z0[t] += (ww).x;                        \
                    z1[t] += (ww).y;                        \
                }                                           \
            }                                               \
        }

    for (int g = 0; g < 255; ++g) {
        // Prefetch group g+1 (independent of current processing).
        const float* Wn = Wl + (size_t)(g + 1) * 4 * HH;
        uint4  nu = Urow[g + 1];
        float2 n0 = *reinterpret_cast<const float2*>(Wn + 0 * HH);
        float2 n1 = *reinterpret_cast<const float2*>(Wn + 1 * HH);
        float2 n2 = *reinterpret_cast<const float2*>(Wn + 2 * HH);
        float2 n3 = *reinterpret_cast<const float2*>(Wn + 3 * HH);

        // Process current group: axons 4g, 4g+1, 4g+2, 4g+3 in ascending order.
        PROC(u4.x, w0)
        PROC(u4.y, w1)
        PROC(u4.z, w2)
        PROC(u4.w, w3)

        u4 = nu; w0 = n0; w1 = n1; w2 = n2; w3 = n3;
    }
    // Last group.
    PROC(u4.x, w0)
    PROC(u4.y, w1)
    PROC(u4.z, w2)
    PROC(u4.w, w3)
    #undef PROC

    // LIF recurrence over 32 cycles, all in registers (bit-exact scalar scan).
    float m0 = 0.0f, m1 = 0.0f;
    unsigned bits0 = 0u, bits1 = 0u;
    #pragma unroll
    for (int t = 0; t < TT; ++t) {
        m0 = __fadd_rn(m0, z0[t]);
        if (thr < m0) { m0 = __fsub_rn(m0, thr); bits0 |= (1u << t); }
        m1 = __fadd_rn(m1, z1[t]);
        if (thr < m1) { m1 = __fsub_rn(m1, thr); bits1 |= (1u << t); }
    }

    const int n0i = ncol * 64 + lane;        // chain 0: k=0
    const int n1i = n0i + 32;                // chain 1: k=1
    if (LAST) {
        out[b * HH + n0i] = (float)__popc(bits0) * (1.0f / 32.0f);
        out[b * HH + n1i] = (float)__popc(bits1) * (1.0f / 32.0f);
    } else {
        Uout[b * HH + n0i] = bits0;
        Uout[b * HH + n1i] = bits1;
    }
}

// ---------------------------------------------------------------------------
// Launch: encode + transpose -> 4 layer passes (ping-pong bitmask buffers).
// ---------------------------------------------------------------------------
extern "C" void kernel_launch(void* const* d_in, const int* in_sizes, int n_in,
                              void* d_out, int out_size)
{
    const float* x   = (const float*)d_in[0];                 // (128,1024)
    const float* Wts = (const float*)d_in[1];                 // (4,1024,1024)
    const float* thr = (const float*)d_in[2];                 // (4,)
    float* out = (float*)d_out;                               // (128,1024)

    static unsigned* pA = nullptr;
    static unsigned* pB = nullptr;
    static float*    pW = nullptr;
    if (!pA) {
        cudaGetSymbolAddress((void**)&pA, g_bitsA);
        cudaGetSymbolAddress((void**)&pB, g_bitsB);
        cudaGetSymbolAddress((void**)&pW, g_Wtp);
    }

    encode_kernel<<<(BB * HH + 255) / 256, 256>>>(x, pA);
    transpose_kernel<<<dim3(HH / 64, HH / 32, LL), 256>>>(Wts, pW);

    const int grid = (BB * HH / 64) / 2;      // 2048 units, 2 warps/block = 1024 blocks (R12 bug: was /64)
    const size_t Ws = (size_t)HH * HH;

    layer_kernel<0><<<grid, 64>>>(pA, pW + 0 * Ws, thr, 0, pB, nullptr);
    layer_kernel<0><<<grid, 64>>>(pB, pW + 1 * Ws, thr, 1, pA, nullptr);
    layer_kernel<0><<<grid, 64>>>(pA, pW + 2 * Ws, thr, 2, pB, nullptr);
    layer_kernel<1><<<grid, 64>>>(pB, pW + 3 * Ws, thr, 3, nullptr, out);
}